// round 15
// baseline (speedup 1.0000x reference)
#include <cuda_runtime.h>
#include <cstdint>

#define N_STEPS 1000
#define ELEMS 6

// Per-step key schedule, 2 uint4 records:
//  A = {k0, k1, k2, k2+1},  B = {k0+2, k1+3, k2+4, k0+5}
__device__ uint4 g_keysA[N_STEPS + 1];
__device__ uint4 g_keysB[N_STEPS + 1];
// central erfinv poly: rebased to s = log2(t), Chebyshev-economized to degree 4,
// computed on-device in double (5 coefficients, low -> high)
__device__ float g_coef[5];

// pre-scale tail erfinv coefficients by 0.1 * sqrt(2)
#define SC(c) (0.14142136f * (c))
// tail threshold in s: z >= 2.5  <=>  s <= -5/ln2
#define S_TAIL (-7.2134752f)

// guaranteed single-instruction FFMA with [0,1] saturation (the clip)
__device__ __forceinline__ float fma_sat(float a, float b, float c) {
    float d;
    asm("fma.rn.sat.f32 %0, %1, %2, %3;" : "=f"(d) : "f"(a), "f"(b), "f"(c));
    return d;
}

// forced IMAD add (fma pipe): d = a*one + b, `one` is an opaque runtime 1
__device__ __forceinline__ uint32_t addm(uint32_t a, uint32_t b, uint32_t one) {
    uint32_t d;
    asm("mad.lo.u32 %0, %1, %2, %3;" : "=r"(d) : "r"(a), "r"(one), "r"(b));
    return d;
}

// ---------------- Threefry-2x32 ----------------
// round with the add forced onto the IMAD pipe; SHF+LOP3 stay on alu
__device__ __forceinline__ void rsm(uint32_t& x0, uint32_t& x1, int r, uint32_t one) {
    x0 = addm(x1, x0, one);                   // IMAD
    x1 = __funnelshift_l(x1, x1, r) ^ x0;     // SHF + LOP3 (alu)
}

// full 20-round block (c0 = 0 folded), returns o0 ^ o1 (partitionable random_bits)
// ALL integer adds (round adds, key injections, counter init) on the IMAD pipe:
// alu carries only the irreducible 20 SHF + 21 LOP3.
__device__ __forceinline__ uint32_t tf_xor(uint4 ka, uint4 kb, uint32_t c1, uint32_t one) {
    uint32_t x1 = addm(c1, ka.y, one);        // IMAD
    uint32_t x0 = addm(x1, ka.x, one);        // round-1 add, x0-init folded (IMAD)
    x1 = __funnelshift_l(x1, x1, 13) ^ x0;
    rsm(x0, x1, 15, one); rsm(x0, x1, 26, one); rsm(x0, x1, 6, one);
    x0 = addm(x0, ka.y, one); x1 = addm(x1, ka.w, one);   // += k1 | += k2+1
    rsm(x0, x1, 17, one); rsm(x0, x1, 29, one); rsm(x0, x1, 16, one); rsm(x0, x1, 24, one);
    x0 = addm(x0, ka.z, one); x1 = addm(x1, kb.x, one);   // += k2 | += k0+2
    rsm(x0, x1, 13, one); rsm(x0, x1, 15, one); rsm(x0, x1, 26, one); rsm(x0, x1, 6, one);
    x0 = addm(x0, ka.x, one); x1 = addm(x1, kb.y, one);   // += k0 | += k1+3
    rsm(x0, x1, 17, one); rsm(x0, x1, 29, one); rsm(x0, x1, 16, one); rsm(x0, x1, 24, one);
    x0 = addm(x0, ka.y, one); x1 = addm(x1, kb.z, one);   // += k1 | += k2+4
    rsm(x0, x1, 13, one); rsm(x0, x1, 15, one); rsm(x0, x1, 26, one); rsm(x0, x1, 6, one);
    return addm(x0, ka.z, one) ^ addm(x1, kb.w, one);     // (x0+k2) ^ (x1+k0+5)
}

// plain scalar threefry for key prep (perf-irrelevant)
__device__ __forceinline__ void rs_s(uint32_t& x0, uint32_t& x1, int r) {
    x0 += x1; x1 = __funnelshift_l(x1, x1, r) ^ x0;
}
__device__ void threefry2x32_full(uint32_t k0, uint32_t k1, uint32_t c0, uint32_t c1,
                                  uint32_t& o0, uint32_t& o1) {
    const uint32_t k2 = k0 ^ k1 ^ 0x1BD11BDAu;
    uint32_t x0 = c0 + k0, x1 = c1 + k1;
    rs_s(x0,x1,13); rs_s(x0,x1,15); rs_s(x0,x1,26); rs_s(x0,x1,6);
    x0 += k1; x1 += k2 + 1u;
    rs_s(x0,x1,17); rs_s(x0,x1,29); rs_s(x0,x1,16); rs_s(x0,x1,24);
    x0 += k2; x1 += k0 + 2u;
    rs_s(x0,x1,13); rs_s(x0,x1,15); rs_s(x0,x1,26); rs_s(x0,x1,6);
    x0 += k0; x1 += k1 + 3u;
    rs_s(x0,x1,17); rs_s(x0,x1,29); rs_s(x0,x1,16); rs_s(x0,x1,24);
    x0 += k1; x1 += k2 + 4u;
    rs_s(x0,x1,13); rs_s(x0,x1,15); rs_s(x0,x1,26); rs_s(x0,x1,6);
    o0 = x0 + k2; o1 = x1 + k0 + 5u;
}

__global__ void prep_keys_kernel() {
    int t = threadIdx.x;
    // thread 0 (double precision):
    //  1) rebase central Giles coefficients from z to s = log2(t):  z = a*s + b
    //  2) Chebyshev-economize degree 5 -> 4 on s in [A, 0], A = -5/ln2
    if (t == 0) {
        const double kk[6] = {1.50140941, 0.246640727, -0.00417768164,
                              -0.00125372503, 0.00021858087, -4.39150654e-06};
        const double a = -0.69314718055994530942;
        const double b = -2.5;
        const int binom[6][6] = {{1,0,0,0,0,0},{1,1,0,0,0,0},{1,2,1,0,0,0},
                                 {1,3,3,1,0,0},{1,4,6,4,1,0},{1,5,10,10,5,1}};
        double cs[6];
        double ai = 1.0;
        for (int i = 0; i < 6; ++i) {
            double sum = 0.0, bp = 1.0;
            for (int m = i; m < 6; ++m) {
                sum += kk[m] * (double)binom[m][i] * bp;
                bp *= b;
            }
            cs[i] = 0.14142136 * ai * sum;
            ai *= a;
        }
        const double A = 5.0 / a;                // -5/ln2
        const double mc = 0.5 * A;
        const double h  = -0.5 * A;
        const double t5[6] = {0.0, 5.0, 0.0, -20.0, 0.0, 16.0};
        double hp[6], mp[6];
        hp[0] = 1.0; mp[0] = 1.0;
        for (int k = 1; k < 6; ++k) { hp[k] = hp[k-1] * h; mp[k] = mp[k-1] * (-mc); }
        double m5[6];
        for (int i = 0; i < 6; ++i) {
            double sum = 0.0;
            for (int k = i; k < 6; ++k)
                sum += t5[k] * (double)binom[k][i] * mp[k-i] / hp[k];
            m5[i] = sum * hp[5] / 16.0;
        }
        for (int i = 0; i < 5; ++i)
            g_coef[i] = (float)(cs[i] - cs[5] * m5[i]);
    }
    if (t > N_STEPS) return;
    uint32_t kk1 = (t < N_STEPS) ? 1u : 2u;
    uint32_t cc1 = (t < N_STEPS) ? (uint32_t)t : 999u;
    uint32_t o0, o1;
    threefry2x32_full(0u, kk1, 0u, cc1, o0, o1);
    uint32_t k0 = o0, k1 = o1, k2 = o0 ^ o1 ^ 0x1BD11BDAu;
    g_keysA[t] = make_uint4(k0, k1, k2, k2 + 1u);
    g_keysB[t] = make_uint4(k0 + 2u, k1 + 3u, k2 + 4u, k0 + 5u);
}

// rare tail branch of erfinv (w >= 5), takes s = log2(t); w = -ln2 * s
// INLINE: avoids CALL/RET overhead on the ~48%-of-warp-iterations fire path
__device__ __forceinline__ float tailp(float s) {
    float w = s * -0.69314718f;
    float zz = __fsqrt_rn(w) - 3.0f;
    float p = SC(-0.000200214257f);
    p = fmaf(p, zz, SC(0.000100950558f));
    p = fmaf(p, zz, SC(0.00134934322f));
    p = fmaf(p, zz, SC(-0.00367342844f));
    p = fmaf(p, zz, SC(0.00573950773f));
    p = fmaf(p, zz, SC(-0.0076224613f));
    p = fmaf(p, zz, SC(0.00943887047f));
    p = fmaf(p, zz, SC(1.00167406f));
    p = fmaf(p, zz, SC(2.83297682f));
    return p;
}

// central pipeline: bits -> {xx, s, p_central}; degree-4 economized poly in s
__device__ __forceinline__ void noise_central(uint32_t b, uint32_t mhi9,
                                              float C0, float C1, float C2,
                                              float C3, float C4,
                                              float& xx, float& s, float& p) {
    uint32_t fbits;   // (b >> 9) | 0x3f800000  ==  hi(b * 2^23) + 0x3f800000, one IMAD.HI
    asm("mad.hi.u32 %0, %1, %2, %3;"
        : "=r"(fbits) : "r"(b), "r"(mhi9), "r"(0x3f800000u));
    float f = __uint_as_float(fbits);                // [1, 2)
    float u = f - 1.0f;                              // [0, 1), exact
    // two-op form REQUIRED: -2.99999994f is not representable (rounds to -3.0f),
    // which would make xx hit exactly -1.0 for bits < 512 -> log(0) -> NaN.
    xx = fmaf(u, 2.0f, -0.99999994f);                // uniform in [nextafter(-1,0), 1)
    float t = fmaf(xx, -xx, 1.0f);                   // 1 - x^2 > 0
    s = __log2f(t);                                  // poly evaluated directly in s
    p = fmaf(C4, s, C3);
    p = fmaf(p, s, C2);
    p = fmaf(p, s, C1);
    p = fmaf(p, s, C0);
}

// 768 threads/SM (3 blocks) -> 85-reg budget: room for 6 fully-parallel chains
__global__ void __launch_bounds__(256, 3)
diffusion_kernel(const float* __restrict__ x, float* __restrict__ out, int n,
                 uint32_t mhi9, uint32_t one) {
    __shared__ uint4 sA[N_STEPS + 1];
    __shared__ uint4 sB[N_STEPS + 1];
    for (int i = threadIdx.x; i <= N_STEPS; i += 256) {
        sA[i] = g_keysA[i];
        sB[i] = g_keysB[i];
    }
    __syncthreads();

    // economized poly coefficients -> registers (uniform broadcast loads, once)
    const float C0 = g_coef[0], C1 = g_coef[1], C2 = g_coef[2];
    const float C3 = g_coef[3], C4 = g_coef[4];

    unsigned tid  = blockIdx.x * 256u + threadIdx.x;
    unsigned base = tid * (unsigned)ELEMS;
    if (base >= (unsigned)n) return;

    if (base + (unsigned)ELEMS <= (unsigned)n) {
        // ---- main path: 6 independent scalar chains per thread (ILP-6) ----
        float v[ELEMS];
        {   // 6 floats = 3x float2 (8-byte aligned)
            const float2* xp = reinterpret_cast<const float2*>(x + base);
            float2 a = xp[0], b = xp[1], c = xp[2];
            v[0] = a.x; v[1] = a.y; v[2] = b.x; v[3] = b.y; v[4] = c.x; v[5] = c.y;
        }
        uint32_t cc[ELEMS];
        #pragma unroll
        for (int j = 0; j < ELEMS; ++j) cc[j] = base + (uint32_t)j;
        const unsigned wmask = __activemask();

        #pragma unroll 4
        for (int t = 0; t < N_STEPS; ++t) {
            uint4 ka = sA[t];
            uint4 kb = sB[t];
            uint32_t b[ELEMS];
            #pragma unroll
            for (int j = 0; j < ELEMS; ++j)
                b[j] = tf_xor(ka, kb, cc[j], one);
            float xx[ELEMS], s[ELEMS], p[ELEMS];
            #pragma unroll
            for (int j = 0; j < ELEMS; ++j)
                noise_central(b[j], mhi9, C0, C1, C2, C3, C4, xx[j], s[j], p[j]);
            // warp-uniform rare guard: no divergence on the common path
            float sm = fminf(fminf(fminf(s[0], s[1]), fminf(s[2], s[3])),
                             fminf(s[4], s[5]));
            if (__builtin_expect(__any_sync(wmask, sm <= S_TAIL), 0)) {
                #pragma unroll
                for (int j = 0; j < ELEMS; ++j)
                    if (s[j] <= S_TAIL) p[j] = tailp(s[j]);
            }
            #pragma unroll
            for (int j = 0; j < ELEMS; ++j)
                v[j] = fma_sat(p[j], xx[j], v[j]);   // clip(v + noise)
        }
        {   // reverse diffusion: single denoise step (subtract)
            uint4 ka = sA[N_STEPS];
            uint4 kb = sB[N_STEPS];
            #pragma unroll
            for (int j = 0; j < ELEMS; ++j) {
                uint32_t b = tf_xor(ka, kb, cc[j], one);
                float xx, s, p;
                noise_central(b, mhi9, C0, C1, C2, C3, C4, xx, s, p);
                if (s <= S_TAIL) p = tailp(s);
                v[j] = fma_sat(-p, xx, v[j]);
            }
        }
        {
            float2* op = reinterpret_cast<float2*>(out + base);
            op[0] = make_float2(v[0], v[1]);
            op[1] = make_float2(v[2], v[3]);
            op[2] = make_float2(v[4], v[5]);
        }
    } else {
        // scalar tail path (not hit when n % 6 == 0, e.g. the 25165824-element shape)
        for (unsigned e = base; e < (unsigned)n; ++e) {
            float vv = x[e];
            for (int t = 0; t < N_STEPS; ++t) {
                float xx, s, p;
                noise_central(tf_xor(sA[t], sB[t], e, one), mhi9,
                              C0, C1, C2, C3, C4, xx, s, p);
                if (s <= S_TAIL) p = tailp(s);
                vv = fma_sat(p, xx, vv);
            }
            float xx, s, p;
            noise_central(tf_xor(sA[N_STEPS], sB[N_STEPS], e, one), mhi9,
                          C0, C1, C2, C3, C4, xx, s, p);
            if (s <= S_TAIL) p = tailp(s);
            out[e] = fma_sat(-p, xx, vv);
        }
    }
}

extern "C" void kernel_launch(void* const* d_in, const int* in_sizes, int n_in,
                              void* d_out, int out_size) {
    const float* x = (const float*)d_in[0];
    float* out     = (float*)d_out;
    int n = out_size;

    prep_keys_kernel<<<1, 1024>>>();

    unsigned threads = (unsigned)((n + ELEMS - 1) / ELEMS);
    unsigned blocks  = (threads + 255u) / 256u;
    // mhi9 = 1<<23 (for IMAD.HI) and one = 1 (for IMAD adds) kept opaque to ptxas
    diffusion_kernel<<<blocks, 256>>>(x, out, n, 1u << 23, 1u);
}

// round 16
// speedup vs baseline: 1.1801x; 1.1801x over previous
#include <cuda_runtime.h>
#include <cstdint>

#define N_STEPS 1000
#define ELEMS 6

// Per-step key schedule, 2 uint4 records:
//  A = {k0, k1, k2, k2+1},  B = {k0+2, k1+3, k2+4, k0+5}
__device__ uint4 g_keysA[N_STEPS + 1];
__device__ uint4 g_keysB[N_STEPS + 1];
// central erfinv poly: rebased to s = log2(t), Chebyshev-economized to degree 4,
// computed on-device in double (5 coefficients, low -> high)
__device__ float g_coef[5];

// pre-scale tail erfinv coefficients by 0.1 * sqrt(2)
#define SC(c) (0.14142136f * (c))
// tail threshold in s: z >= 2.5  <=>  s <= -5/ln2
#define S_TAIL (-7.2134752f)

// guaranteed single-instruction FFMA with [0,1] saturation (the clip)
__device__ __forceinline__ float fma_sat(float a, float b, float c) {
    float d;
    asm("fma.rn.sat.f32 %0, %1, %2, %3;" : "=f"(d) : "f"(a), "f"(b), "f"(c));
    return d;
}

// forced IMAD add (fma pipe): d = a*one + b, `one` is an opaque runtime 1
__device__ __forceinline__ uint32_t addm(uint32_t a, uint32_t b, uint32_t one) {
    uint32_t d;
    asm("mad.lo.u32 %0, %1, %2, %3;" : "=r"(d) : "r"(a), "r"(one), "r"(b));
    return d;
}

// ---------------- Threefry-2x32 ----------------
// round with the add forced onto the IMAD pipe; SHF+LOP3 stay on alu
__device__ __forceinline__ void rsm(uint32_t& x0, uint32_t& x1, int r, uint32_t one) {
    x0 = addm(x1, x0, one);                   // IMAD
    x1 = __funnelshift_l(x1, x1, r) ^ x0;     // SHF + LOP3 (alu)
}

// full 20-round block (c0 = 0 folded), returns o0 ^ o1 (partitionable random_bits)
// ALL integer adds (round adds, key injections, counter init) on the IMAD pipe:
// alu carries only the irreducible 20 SHF + 21 LOP3.
__device__ __forceinline__ uint32_t tf_xor(uint4 ka, uint4 kb, uint32_t c1, uint32_t one) {
    uint32_t x1 = addm(c1, ka.y, one);        // IMAD
    uint32_t x0 = addm(x1, ka.x, one);        // round-1 add, x0-init folded (IMAD)
    x1 = __funnelshift_l(x1, x1, 13) ^ x0;
    rsm(x0, x1, 15, one); rsm(x0, x1, 26, one); rsm(x0, x1, 6, one);
    x0 = addm(x0, ka.y, one); x1 = addm(x1, ka.w, one);   // += k1 | += k2+1
    rsm(x0, x1, 17, one); rsm(x0, x1, 29, one); rsm(x0, x1, 16, one); rsm(x0, x1, 24, one);
    x0 = addm(x0, ka.z, one); x1 = addm(x1, kb.x, one);   // += k2 | += k0+2
    rsm(x0, x1, 13, one); rsm(x0, x1, 15, one); rsm(x0, x1, 26, one); rsm(x0, x1, 6, one);
    x0 = addm(x0, ka.x, one); x1 = addm(x1, kb.y, one);   // += k0 | += k1+3
    rsm(x0, x1, 17, one); rsm(x0, x1, 29, one); rsm(x0, x1, 16, one); rsm(x0, x1, 24, one);
    x0 = addm(x0, ka.y, one); x1 = addm(x1, kb.z, one);   // += k1 | += k2+4
    rsm(x0, x1, 13, one); rsm(x0, x1, 15, one); rsm(x0, x1, 26, one); rsm(x0, x1, 6, one);
    return addm(x0, ka.z, one) ^ addm(x1, kb.w, one);     // (x0+k2) ^ (x1+k0+5)
}

// plain scalar threefry for key prep (perf-irrelevant)
__device__ __forceinline__ void rs_s(uint32_t& x0, uint32_t& x1, int r) {
    x0 += x1; x1 = __funnelshift_l(x1, x1, r) ^ x0;
}
__device__ void threefry2x32_full(uint32_t k0, uint32_t k1, uint32_t c0, uint32_t c1,
                                  uint32_t& o0, uint32_t& o1) {
    const uint32_t k2 = k0 ^ k1 ^ 0x1BD11BDAu;
    uint32_t x0 = c0 + k0, x1 = c1 + k1;
    rs_s(x0,x1,13); rs_s(x0,x1,15); rs_s(x0,x1,26); rs_s(x0,x1,6);
    x0 += k1; x1 += k2 + 1u;
    rs_s(x0,x1,17); rs_s(x0,x1,29); rs_s(x0,x1,16); rs_s(x0,x1,24);
    x0 += k2; x1 += k0 + 2u;
    rs_s(x0,x1,13); rs_s(x0,x1,15); rs_s(x0,x1,26); rs_s(x0,x1,6);
    x0 += k0; x1 += k1 + 3u;
    rs_s(x0,x1,17); rs_s(x0,x1,29); rs_s(x0,x1,16); rs_s(x0,x1,24);
    x0 += k1; x1 += k2 + 4u;
    rs_s(x0,x1,13); rs_s(x0,x1,15); rs_s(x0,x1,26); rs_s(x0,x1,6);
    o0 = x0 + k2; o1 = x1 + k0 + 5u;
}

__global__ void prep_keys_kernel() {
    int t = threadIdx.x;
    // thread 0 (double precision):
    //  1) rebase central Giles coefficients from z to s = log2(t):  z = a*s + b
    //  2) Chebyshev-economize degree 5 -> 4 on s in [A, 0], A = -5/ln2
    if (t == 0) {
        const double kk[6] = {1.50140941, 0.246640727, -0.00417768164,
                              -0.00125372503, 0.00021858087, -4.39150654e-06};
        const double a = -0.69314718055994530942;
        const double b = -2.5;
        const int binom[6][6] = {{1,0,0,0,0,0},{1,1,0,0,0,0},{1,2,1,0,0,0},
                                 {1,3,3,1,0,0},{1,4,6,4,1,0},{1,5,10,10,5,1}};
        double cs[6];
        double ai = 1.0;
        for (int i = 0; i < 6; ++i) {
            double sum = 0.0, bp = 1.0;
            for (int m = i; m < 6; ++m) {
                sum += kk[m] * (double)binom[m][i] * bp;
                bp *= b;
            }
            cs[i] = 0.14142136 * ai * sum;
            ai *= a;
        }
        const double A = 5.0 / a;                // -5/ln2
        const double mc = 0.5 * A;
        const double h  = -0.5 * A;
        const double t5[6] = {0.0, 5.0, 0.0, -20.0, 0.0, 16.0};
        double hp[6], mp[6];
        hp[0] = 1.0; mp[0] = 1.0;
        for (int k = 1; k < 6; ++k) { hp[k] = hp[k-1] * h; mp[k] = mp[k-1] * (-mc); }
        double m5[6];
        for (int i = 0; i < 6; ++i) {
            double sum = 0.0;
            for (int k = i; k < 6; ++k)
                sum += t5[k] * (double)binom[k][i] * mp[k-i] / hp[k];
            m5[i] = sum * hp[5] / 16.0;
        }
        for (int i = 0; i < 5; ++i)
            g_coef[i] = (float)(cs[i] - cs[5] * m5[i]);
    }
    if (t > N_STEPS) return;
    uint32_t kk1 = (t < N_STEPS) ? 1u : 2u;
    uint32_t cc1 = (t < N_STEPS) ? (uint32_t)t : 999u;
    uint32_t o0, o1;
    threefry2x32_full(0u, kk1, 0u, cc1, o0, o1);
    uint32_t k0 = o0, k1 = o1, k2 = o0 ^ o1 ^ 0x1BD11BDAu;
    g_keysA[t] = make_uint4(k0, k1, k2, k2 + 1u);
    g_keysB[t] = make_uint4(k0 + 2u, k1 + 3u, k2 + 4u, k0 + 5u);
}

// rare tail branch of erfinv (w >= 5), takes s = log2(t); w = -ln2 * s
// __noinline__ is deliberate (R15 inlining exploded live ranges -> 18% regression)
__device__ __noinline__ float tailp(float s) {
    float w = s * -0.69314718f;
    float zz = __fsqrt_rn(w) - 3.0f;
    float p = SC(-0.000200214257f);
    p = fmaf(p, zz, SC(0.000100950558f));
    p = fmaf(p, zz, SC(0.00134934322f));
    p = fmaf(p, zz, SC(-0.00367342844f));
    p = fmaf(p, zz, SC(0.00573950773f));
    p = fmaf(p, zz, SC(-0.0076224613f));
    p = fmaf(p, zz, SC(0.00943887047f));
    p = fmaf(p, zz, SC(1.00167406f));
    p = fmaf(p, zz, SC(2.83297682f));
    return p;
}

// central pipeline: bits -> {xx, s, p_central}; degree-4 economized poly in s
__device__ __forceinline__ void noise_central(uint32_t b, uint32_t mhi9,
                                              float C0, float C1, float C2,
                                              float C3, float C4,
                                              float& xx, float& s, float& p) {
    uint32_t fbits;   // (b >> 9) | 0x3f800000  ==  hi(b * 2^23) + 0x3f800000, one IMAD.HI
    asm("mad.hi.u32 %0, %1, %2, %3;"
        : "=r"(fbits) : "r"(b), "r"(mhi9), "r"(0x3f800000u));
    float f = __uint_as_float(fbits);                // [1, 2)
    float u = f - 1.0f;                              // [0, 1), exact
    // two-op form REQUIRED: -2.99999994f is not representable (rounds to -3.0f),
    // which would make xx hit exactly -1.0 for bits < 512 -> log(0) -> NaN.
    xx = fmaf(u, 2.0f, -0.99999994f);                // uniform in [nextafter(-1,0), 1)
    float t = fmaf(xx, -xx, 1.0f);                   // 1 - x^2 > 0
    s = __log2f(t);                                  // poly evaluated directly in s
    p = fmaf(C4, s, C3);
    p = fmaf(p, s, C2);
    p = fmaf(p, s, C1);
    p = fmaf(p, s, C0);
}

// 768 threads/SM (3 blocks) -> 85-reg budget: room for 6 fully-parallel chains
__global__ void __launch_bounds__(256, 3)
diffusion_kernel(const float* __restrict__ x, float* __restrict__ out, int n,
                 uint32_t mhi9, uint32_t one) {
    __shared__ uint4 sA[N_STEPS + 1];
    __shared__ uint4 sB[N_STEPS + 1];
    for (int i = threadIdx.x; i <= N_STEPS; i += 256) {
        sA[i] = g_keysA[i];
        sB[i] = g_keysB[i];
    }
    __syncthreads();

    // economized poly coefficients -> registers (uniform broadcast loads, once)
    const float C0 = g_coef[0], C1 = g_coef[1], C2 = g_coef[2];
    const float C3 = g_coef[3], C4 = g_coef[4];

    unsigned tid  = blockIdx.x * 256u + threadIdx.x;
    unsigned base = tid * (unsigned)ELEMS;
    if (base >= (unsigned)n) return;

    if (base + (unsigned)ELEMS <= (unsigned)n) {
        // ---- main path: 6 independent scalar chains per thread (ILP-6) ----
        float v[ELEMS];
        {   // 6 floats = 3x float2 (8-byte aligned)
            const float2* xp = reinterpret_cast<const float2*>(x + base);
            float2 a = xp[0], b = xp[1], c = xp[2];
            v[0] = a.x; v[1] = a.y; v[2] = b.x; v[3] = b.y; v[4] = c.x; v[5] = c.y;
        }
        uint32_t cc[ELEMS];
        #pragma unroll
        for (int j = 0; j < ELEMS; ++j) cc[j] = base + (uint32_t)j;
        const unsigned wmask = __activemask();

        #pragma unroll 2
        for (int t = 0; t < N_STEPS; ++t) {
            uint4 ka = sA[t];
            uint4 kb = sB[t];
            uint32_t b[ELEMS];
            #pragma unroll
            for (int j = 0; j < ELEMS; ++j)
                b[j] = tf_xor(ka, kb, cc[j], one);
            float xx[ELEMS], s[ELEMS], p[ELEMS];
            #pragma unroll
            for (int j = 0; j < ELEMS; ++j)
                noise_central(b[j], mhi9, C0, C1, C2, C3, C4, xx[j], s[j], p[j]);
            // warp-uniform rare guard: no divergence on the common path
            float sm = fminf(fminf(fminf(s[0], s[1]), fminf(s[2], s[3])),
                             fminf(s[4], s[5]));
            if (__builtin_expect(__any_sync(wmask, sm <= S_TAIL), 0)) {
                #pragma unroll
                for (int j = 0; j < ELEMS; ++j)
                    if (s[j] <= S_TAIL) p[j] = tailp(s[j]);
            }
            #pragma unroll
            for (int j = 0; j < ELEMS; ++j)
                v[j] = fma_sat(p[j], xx[j], v[j]);   // clip(v + noise)
        }
        {   // reverse diffusion: single denoise step (subtract)
            uint4 ka = sA[N_STEPS];
            uint4 kb = sB[N_STEPS];
            #pragma unroll
            for (int j = 0; j < ELEMS; ++j) {
                uint32_t b = tf_xor(ka, kb, cc[j], one);
                float xx, s, p;
                noise_central(b, mhi9, C0, C1, C2, C3, C4, xx, s, p);
                if (s <= S_TAIL) p = tailp(s);
                v[j] = fma_sat(-p, xx, v[j]);
            }
        }
        {
            float2* op = reinterpret_cast<float2*>(out + base);
            op[0] = make_float2(v[0], v[1]);
            op[1] = make_float2(v[2], v[3]);
            op[2] = make_float2(v[4], v[5]);
        }
    } else {
        // scalar tail path (not hit when n % 6 == 0, e.g. the 25165824-element shape)
        for (unsigned e = base; e < (unsigned)n; ++e) {
            float vv = x[e];
            for (int t = 0; t < N_STEPS; ++t) {
                float xx, s, p;
                noise_central(tf_xor(sA[t], sB[t], e, one), mhi9,
                              C0, C1, C2, C3, C4, xx, s, p);
                if (s <= S_TAIL) p = tailp(s);
                vv = fma_sat(p, xx, vv);
            }
            float xx, s, p;
            noise_central(tf_xor(sA[N_STEPS], sB[N_STEPS], e, one), mhi9,
                          C0, C1, C2, C3, C4, xx, s, p);
            if (s <= S_TAIL) p = tailp(s);
            out[e] = fma_sat(-p, xx, vv);
        }
    }
}

extern "C" void kernel_launch(void* const* d_in, const int* in_sizes, int n_in,
                              void* d_out, int out_size) {
    const float* x = (const float*)d_in[0];
    float* out     = (float*)d_out;
    int n = out_size;

    prep_keys_kernel<<<1, 1024>>>();

    unsigned threads = (unsigned)((n + ELEMS - 1) / ELEMS);
    unsigned blocks  = (threads + 255u) / 256u;
    // mhi9 = 1<<23 (for IMAD.HI) and one = 1 (for IMAD adds) kept opaque to ptxas
    diffusion_kernel<<<blocks, 256>>>(x, out, n, 1u << 23, 1u);
}

// round 17
// speedup vs baseline: 1.1909x; 1.0092x over previous
#include <cuda_runtime.h>
#include <cstdint>

#define N_STEPS 1000
#define ELEMS 6

// Per-step key schedule, 2 uint4 records:
//  A = {k0, k1, k2, k2+1},  B = {k0+2, k1+3, k2+4, k0+5}
__device__ uint4 g_keysA[N_STEPS + 1];
__device__ uint4 g_keysB[N_STEPS + 1];
// central erfinv poly: degree-6 Chebyshev interpolant of 0.1*sqrt(2)*erfinv(x)/x
// in s = log2(1-x^2) on [-11, 0], built on-device in double (7 coefs, low->high)
__device__ float g_coef[7];

// pre-scale tail erfinv coefficients by 0.1 * sqrt(2)
#define SC(c) (0.14142136f * (c))
// tail threshold in s: w >= 11*ln2 ~ 7.62  <=>  s <= -11
#define S_TAIL (-11.0f)

// guaranteed single-instruction FFMA with [0,1] saturation (the clip)
__device__ __forceinline__ float fma_sat(float a, float b, float c) {
    float d;
    asm("fma.rn.sat.f32 %0, %1, %2, %3;" : "=f"(d) : "f"(a), "f"(b), "f"(c));
    return d;
}

// forced IMAD add (fma pipe): d = a*one + b, `one` is an opaque runtime 1
__device__ __forceinline__ uint32_t addm(uint32_t a, uint32_t b, uint32_t one) {
    uint32_t d;
    asm("mad.lo.u32 %0, %1, %2, %3;" : "=r"(d) : "r"(a), "r"(one), "r"(b));
    return d;
}

// ---------------- Threefry-2x32 ----------------
// round with the add forced onto the IMAD pipe; SHF+LOP3 stay on alu
__device__ __forceinline__ void rsm(uint32_t& x0, uint32_t& x1, int r, uint32_t one) {
    x0 = addm(x1, x0, one);                   // IMAD
    x1 = __funnelshift_l(x1, x1, r) ^ x0;     // SHF + LOP3 (alu)
}

// full 20-round block (c0 = 0 folded), returns o0 ^ o1 (partitionable random_bits)
// ALL integer adds on the IMAD pipe: alu carries only the 20 SHF + 21 LOP3.
__device__ __forceinline__ uint32_t tf_xor(uint4 ka, uint4 kb, uint32_t c1, uint32_t one) {
    uint32_t x1 = addm(c1, ka.y, one);        // IMAD
    uint32_t x0 = addm(x1, ka.x, one);        // round-1 add, x0-init folded (IMAD)
    x1 = __funnelshift_l(x1, x1, 13) ^ x0;
    rsm(x0, x1, 15, one); rsm(x0, x1, 26, one); rsm(x0, x1, 6, one);
    x0 = addm(x0, ka.y, one); x1 = addm(x1, ka.w, one);   // += k1 | += k2+1
    rsm(x0, x1, 17, one); rsm(x0, x1, 29, one); rsm(x0, x1, 16, one); rsm(x0, x1, 24, one);
    x0 = addm(x0, ka.z, one); x1 = addm(x1, kb.x, one);   // += k2 | += k0+2
    rsm(x0, x1, 13, one); rsm(x0, x1, 15, one); rsm(x0, x1, 26, one); rsm(x0, x1, 6, one);
    x0 = addm(x0, ka.x, one); x1 = addm(x1, kb.y, one);   // += k0 | += k1+3
    rsm(x0, x1, 17, one); rsm(x0, x1, 29, one); rsm(x0, x1, 16, one); rsm(x0, x1, 24, one);
    x0 = addm(x0, ka.y, one); x1 = addm(x1, kb.z, one);   // += k1 | += k2+4
    rsm(x0, x1, 13, one); rsm(x0, x1, 15, one); rsm(x0, x1, 26, one); rsm(x0, x1, 6, one);
    return addm(x0, ka.z, one) ^ addm(x1, kb.w, one);     // (x0+k2) ^ (x1+k0+5)
}

// plain scalar threefry for key prep (perf-irrelevant)
__device__ __forceinline__ void rs_s(uint32_t& x0, uint32_t& x1, int r) {
    x0 += x1; x1 = __funnelshift_l(x1, x1, r) ^ x0;
}
__device__ void threefry2x32_full(uint32_t k0, uint32_t k1, uint32_t c0, uint32_t c1,
                                  uint32_t& o0, uint32_t& o1) {
    const uint32_t k2 = k0 ^ k1 ^ 0x1BD11BDAu;
    uint32_t x0 = c0 + k0, x1 = c1 + k1;
    rs_s(x0,x1,13); rs_s(x0,x1,15); rs_s(x0,x1,26); rs_s(x0,x1,6);
    x0 += k1; x1 += k2 + 1u;
    rs_s(x0,x1,17); rs_s(x0,x1,29); rs_s(x0,x1,16); rs_s(x0,x1,24);
    x0 += k2; x1 += k0 + 2u;
    rs_s(x0,x1,13); rs_s(x0,x1,15); rs_s(x0,x1,26); rs_s(x0,x1,6);
    x0 += k0; x1 += k1 + 3u;
    rs_s(x0,x1,17); rs_s(x0,x1,29); rs_s(x0,x1,16); rs_s(x0,x1,24);
    x0 += k1; x1 += k2 + 4u;
    rs_s(x0,x1,13); rs_s(x0,x1,15); rs_s(x0,x1,26); rs_s(x0,x1,6);
    o0 = x0 + k2; o1 = x1 + k0 + 5u;
}

__global__ void prep_keys_kernel() {
    int t = threadIdx.x;
    // thread 0 (double precision): degree-6 Chebyshev interpolation of
    //   g(s) = 0.1*sqrt(2) * erfinv(x)/x,  x = sqrt(1 - 2^s),  s in [-11, 0]
    // via 7 Chebyshev nodes -> Newton divided differences -> monomial coefs.
    if (t == 0) {
        const double PI = 3.14159265358979323846;
        const double SCALE = 0.14142135623730951;   // 0.1 * sqrt(2)
        const double mid = -5.5, half = 5.5;        // interval [-11, 0]
        double sn[7], gv[7];
        for (int k = 0; k < 7; ++k) {
            sn[k] = mid + half * cos((2.0 * k + 1.0) * PI / 14.0);
            double tt = exp2(sn[k]);
            double xv = sqrt(1.0 - tt);
            gv[k] = SCALE * erfinv(xv) / xv;
        }
        // Newton divided differences (in place)
        for (int j = 1; j < 7; ++j)
            for (int k = 6; k >= j; --k)
                gv[k] = (gv[k] - gv[k-1]) / (sn[k] - sn[k-j]);
        // expand Newton form to monomial:  p = (...((dd6)(s-s5)+dd5)...)(s-s0)+dd0
        double mono[7] = {gv[6], 0, 0, 0, 0, 0, 0};
        int deg = 0;
        for (int i = 5; i >= 0; --i) {
            double nm[7];
            nm[0] = -sn[i] * mono[0] + gv[i];
            for (int d = 1; d <= deg; ++d)
                nm[d] = mono[d-1] - sn[i] * mono[d];
            nm[deg + 1] = mono[deg];
            deg++;
            for (int d = 0; d <= deg; ++d) mono[d] = nm[d];
        }
        for (int i = 0; i < 7; ++i)
            g_coef[i] = (float)mono[i];
    }
    if (t > N_STEPS) return;
    uint32_t kk1 = (t < N_STEPS) ? 1u : 2u;
    uint32_t cc1 = (t < N_STEPS) ? (uint32_t)t : 999u;
    uint32_t o0, o1;
    threefry2x32_full(0u, kk1, 0u, cc1, o0, o1);
    uint32_t k0 = o0, k1 = o1, k2 = o0 ^ o1 ^ 0x1BD11BDAu;
    g_keysA[t] = make_uint4(k0, k1, k2, k2 + 1u);
    g_keysB[t] = make_uint4(k0 + 2u, k1 + 3u, k2 + 4u, k0 + 5u);
}

// ultra-rare tail branch (w >= 11*ln2 ~ 7.62, P ~ 2.4e-4/sample); takes s
// Giles tail fit (valid w >= 5 superset). __noinline__: keep hot-loop regs small.
__device__ __noinline__ float tailp(float s) {
    float w = s * -0.69314718f;
    float zz = __fsqrt_rn(w) - 3.0f;
    float p = SC(-0.000200214257f);
    p = fmaf(p, zz, SC(0.000100950558f));
    p = fmaf(p, zz, SC(0.00134934322f));
    p = fmaf(p, zz, SC(-0.00367342844f));
    p = fmaf(p, zz, SC(0.00573950773f));
    p = fmaf(p, zz, SC(-0.0076224613f));
    p = fmaf(p, zz, SC(0.00943887047f));
    p = fmaf(p, zz, SC(1.00167406f));
    p = fmaf(p, zz, SC(2.83297682f));
    return p;
}

// central pipeline: bits -> {xx, s, p}; degree-6 poly in s on [-11, 0]
__device__ __forceinline__ void noise_central(uint32_t b, uint32_t mhi9,
                                              float C0, float C1, float C2, float C3,
                                              float C4, float C5, float C6,
                                              float& xx, float& s, float& p) {
    uint32_t fbits;   // (b >> 9) | 0x3f800000  ==  hi(b * 2^23) + 0x3f800000, one IMAD.HI
    asm("mad.hi.u32 %0, %1, %2, %3;"
        : "=r"(fbits) : "r"(b), "r"(mhi9), "r"(0x3f800000u));
    float f = __uint_as_float(fbits);                // [1, 2)
    float u = f - 1.0f;                              // [0, 1), exact
    // two-op form REQUIRED: -2.99999994f is not representable (rounds to -3.0f),
    // which would make xx hit exactly -1.0 for bits < 512 -> log(0) -> NaN.
    xx = fmaf(u, 2.0f, -0.99999994f);                // uniform in [nextafter(-1,0), 1)
    float t = fmaf(xx, -xx, 1.0f);                   // 1 - x^2 > 0
    s = __log2f(t);                                  // poly evaluated directly in s
    p = fmaf(C6, s, C5);
    p = fmaf(p, s, C4);
    p = fmaf(p, s, C3);
    p = fmaf(p, s, C2);
    p = fmaf(p, s, C1);
    p = fmaf(p, s, C0);
}

// 768 threads/SM (3 blocks) -> 85-reg budget: room for 6 fully-parallel chains
__global__ void __launch_bounds__(256, 3)
diffusion_kernel(const float* __restrict__ x, float* __restrict__ out, int n,
                 uint32_t mhi9, uint32_t one) {
    __shared__ uint4 sA[N_STEPS + 1];
    __shared__ uint4 sB[N_STEPS + 1];
    for (int i = threadIdx.x; i <= N_STEPS; i += 256) {
        sA[i] = g_keysA[i];
        sB[i] = g_keysB[i];
    }
    __syncthreads();

    // poly coefficients -> registers (uniform broadcast loads, once)
    const float C0 = g_coef[0], C1 = g_coef[1], C2 = g_coef[2], C3 = g_coef[3];
    const float C4 = g_coef[4], C5 = g_coef[5], C6 = g_coef[6];

    unsigned tid  = blockIdx.x * 256u + threadIdx.x;
    unsigned base = tid * (unsigned)ELEMS;
    if (base >= (unsigned)n) return;

    if (base + (unsigned)ELEMS <= (unsigned)n) {
        // ---- main path: 6 independent scalar chains per thread (ILP-6) ----
        float v[ELEMS];
        {   // 6 floats = 3x float2 (8-byte aligned)
            const float2* xp = reinterpret_cast<const float2*>(x + base);
            float2 a = xp[0], b = xp[1], c = xp[2];
            v[0] = a.x; v[1] = a.y; v[2] = b.x; v[3] = b.y; v[4] = c.x; v[5] = c.y;
        }
        uint32_t cc[ELEMS];
        #pragma unroll
        for (int j = 0; j < ELEMS; ++j) cc[j] = base + (uint32_t)j;
        const unsigned wmask = __activemask();

        #pragma unroll 2
        for (int t = 0; t < N_STEPS; ++t) {
            uint4 ka = sA[t];
            uint4 kb = sB[t];
            uint32_t b[ELEMS];
            #pragma unroll
            for (int j = 0; j < ELEMS; ++j)
                b[j] = tf_xor(ka, kb, cc[j], one);
            float xx[ELEMS], s[ELEMS], p[ELEMS];
            #pragma unroll
            for (int j = 0; j < ELEMS; ++j)
                noise_central(b[j], mhi9, C0, C1, C2, C3, C4, C5, C6,
                              xx[j], s[j], p[j]);
            // warp-uniform ultra-rare guard (fires ~4.5% of warp-steps)
            float sm = fminf(fminf(fminf(s[0], s[1]), fminf(s[2], s[3])),
                             fminf(s[4], s[5]));
            if (__builtin_expect(__any_sync(wmask, sm <= S_TAIL), 0)) {
                #pragma unroll
                for (int j = 0; j < ELEMS; ++j)
                    if (s[j] <= S_TAIL) p[j] = tailp(s[j]);
            }
            #pragma unroll
            for (int j = 0; j < ELEMS; ++j)
                v[j] = fma_sat(p[j], xx[j], v[j]);   // clip(v + noise)
        }
        {   // reverse diffusion: single denoise step (subtract)
            uint4 ka = sA[N_STEPS];
            uint4 kb = sB[N_STEPS];
            #pragma unroll
            for (int j = 0; j < ELEMS; ++j) {
                uint32_t b = tf_xor(ka, kb, cc[j], one);
                float xx, s, p;
                noise_central(b, mhi9, C0, C1, C2, C3, C4, C5, C6, xx, s, p);
                if (s <= S_TAIL) p = tailp(s);
                v[j] = fma_sat(-p, xx, v[j]);
            }
        }
        {
            float2* op = reinterpret_cast<float2*>(out + base);
            op[0] = make_float2(v[0], v[1]);
            op[1] = make_float2(v[2], v[3]);
            op[2] = make_float2(v[4], v[5]);
        }
    } else {
        // scalar tail path (not hit when n % 6 == 0, e.g. the 25165824-element shape)
        for (unsigned e = base; e < (unsigned)n; ++e) {
            float vv = x[e];
            for (int t = 0; t < N_STEPS; ++t) {
                float xx, s, p;
                noise_central(tf_xor(sA[t], sB[t], e, one), mhi9,
                              C0, C1, C2, C3, C4, C5, C6, xx, s, p);
                if (s <= S_TAIL) p = tailp(s);
                vv = fma_sat(p, xx, vv);
            }
            float xx, s, p;
            noise_central(tf_xor(sA[N_STEPS], sB[N_STEPS], e, one), mhi9,
                          C0, C1, C2, C3, C4, C5, C6, xx, s, p);
            if (s <= S_TAIL) p = tailp(s);
            out[e] = fma_sat(-p, xx, vv);
        }
    }
}

extern "C" void kernel_launch(void* const* d_in, const int* in_sizes, int n_in,
                              void* d_out, int out_size) {
    const float* x = (const float*)d_in[0];
    float* out     = (float*)d_out;
    int n = out_size;

    prep_keys_kernel<<<1, 1024>>>();

    unsigned threads = (unsigned)((n + ELEMS - 1) / ELEMS);
    unsigned blocks  = (threads + 255u) / 256u;
    // mhi9 = 1<<23 (for IMAD.HI) and one = 1 (for IMAD adds) kept opaque to ptxas
    diffusion_kernel<<<blocks, 256>>>(x, out, n, 1u << 23, 1u);
}